// round 1
// baseline (speedup 1.0000x reference)
#include <cuda_runtime.h>

#define N_NODES 100000
#define N_EDGES 1600000
#define D_IN    256
#define D_HID   64
#define D_OUT   32
#define NUM_PROP 10
#define ALPHA   0.1f

// ---------------- device scratch (no allocations allowed) ----------------
__device__ int   g_cnt[N_NODES];          // histogram, then scatter cursors
__device__ int   g_rowptr[N_NODES + 1];   // CSR row pointers
__device__ int2  g_edges[N_EDGES];        // packed (col, __float_as_int(val)), row-sorted
__device__ float g_H [(size_t)N_NODES * D_HID];   // hidden activations
__device__ float g_x0[(size_t)N_NODES * D_OUT];   // MLP output / teleport term
__device__ float g_bufA[(size_t)N_NODES * D_OUT];
__device__ float g_bufB[(size_t)N_NODES * D_OUT];

// ---------------- MLP stage 1: H = relu(F @ W1 + b1) ----------------
// thread = one node; W1 read via __ldg (broadcast, L1/L2 resident: 64 KB)
__global__ __launch_bounds__(128) void k_mlp1(const float* __restrict__ F,
                                              const float* __restrict__ W1,
                                              const float* __restrict__ b1) {
    int node = blockIdx.x * 128 + threadIdx.x;
    if (node >= N_NODES) return;

    float acc[D_HID];
#pragma unroll
    for (int h = 0; h < D_HID; h += 4) {
        float4 b = __ldg((const float4*)(b1 + h));
        acc[h] = b.x; acc[h+1] = b.y; acc[h+2] = b.z; acc[h+3] = b.w;
    }

    const float4* Fr  = (const float4*)(F + (size_t)node * D_IN);
    const float4* W14 = (const float4*)W1;

    for (int k4 = 0; k4 < D_IN / 4; k4++) {
        float4 f = __ldg(&Fr[k4]);
        float fv[4] = {f.x, f.y, f.z, f.w};
#pragma unroll
        for (int s = 0; s < 4; s++) {
            int k = k4 * 4 + s;
            const float4* wrow = &W14[k * (D_HID / 4)];
#pragma unroll
            for (int j = 0; j < D_HID / 4; j++) {
                float4 w = __ldg(&wrow[j]);
                acc[4*j]   += fv[s] * w.x;
                acc[4*j+1] += fv[s] * w.y;
                acc[4*j+2] += fv[s] * w.z;
                acc[4*j+3] += fv[s] * w.w;
            }
        }
    }

    float4* Hr = (float4*)(g_H + (size_t)node * D_HID);
#pragma unroll
    for (int j = 0; j < D_HID / 4; j++) {
        float4 o;
        o.x = fmaxf(acc[4*j],   0.f);
        o.y = fmaxf(acc[4*j+1], 0.f);
        o.z = fmaxf(acc[4*j+2], 0.f);
        o.w = fmaxf(acc[4*j+3], 0.f);
        Hr[j] = o;
    }
}

// ---------------- MLP stage 2: x0 = H @ W2 + b2 ----------------
__global__ __launch_bounds__(128) void k_mlp2(const float* __restrict__ W2,
                                              const float* __restrict__ b2) {
    __shared__ float sW2[D_HID * D_OUT];
    for (int i = threadIdx.x; i < D_HID * D_OUT; i += 128) sW2[i] = W2[i];
    __syncthreads();

    int node = blockIdx.x * 128 + threadIdx.x;
    if (node >= N_NODES) return;

    float o[D_OUT];
#pragma unroll
    for (int c = 0; c < D_OUT; c++) o[c] = __ldg(&b2[c]);

    const float4* Hr = (const float4*)(g_H + (size_t)node * D_HID);
    for (int j = 0; j < D_HID / 4; j++) {
        float4 h4 = Hr[j];
        float hv[4] = {h4.x, h4.y, h4.z, h4.w};
#pragma unroll
        for (int s = 0; s < 4; s++) {
            const float* w = &sW2[(4*j + s) * D_OUT];
#pragma unroll
            for (int c = 0; c < D_OUT; c++) o[c] += hv[s] * w[c];
        }
    }

    float4* X = (float4*)(g_x0 + (size_t)node * D_OUT);
#pragma unroll
    for (int j = 0; j < D_OUT / 4; j++)
        X[j] = make_float4(o[4*j], o[4*j+1], o[4*j+2], o[4*j+3]);
}

// ---------------- CSR build ----------------
__global__ void k_zero_cnt() {
    int i = blockIdx.x * blockDim.x + threadIdx.x;
    if (i < N_NODES) g_cnt[i] = 0;
}

__global__ void k_hist(const int* __restrict__ row) {
    int e = blockIdx.x * blockDim.x + threadIdx.x;
    if (e < N_EDGES) atomicAdd(&g_cnt[row[e]], 1);
}

// single-block exclusive scan over g_cnt -> g_rowptr; also re-initializes
// g_cnt[i] to the exclusive prefix (scatter cursor).
__global__ __launch_bounds__(1024) void k_scan() {
    __shared__ int s[1024];
    __shared__ int s_carry;
    int tid = threadIdx.x;
    if (tid == 0) s_carry = 0;
    __syncthreads();

    for (int base = 0; base < N_NODES; base += 1024) {
        int i = base + tid;
        int v = (i < N_NODES) ? g_cnt[i] : 0;
        s[tid] = v;
        __syncthreads();
        // Hillis-Steele inclusive scan
        for (int off = 1; off < 1024; off <<= 1) {
            int t = (tid >= off) ? s[tid - off] : 0;
            __syncthreads();
            s[tid] += t;
            __syncthreads();
        }
        int incl  = s[tid];
        int carry = s_carry;
        if (i < N_NODES) {
            int excl = carry + incl - v;
            g_rowptr[i] = excl;
            g_cnt[i]    = excl;   // cursor for scatter
        }
        __syncthreads();
        if (tid == 1023) s_carry = carry + incl;
        __syncthreads();
    }
    if (tid == 0) g_rowptr[N_NODES] = s_carry;  // == N_EDGES
}

__global__ void k_scatter(const int* __restrict__ row,
                          const int* __restrict__ col,
                          const float* __restrict__ val) {
    int e = blockIdx.x * blockDim.x + threadIdx.x;
    if (e < N_EDGES) {
        int r = row[e];
        int p = atomicAdd(&g_cnt[r], 1);
        g_edges[p] = make_int2(col[e], __float_as_int(val[e]));
    }
}

// ---------------- propagation: warp-per-row, lane = output dim ----------------
// x_{t+1}[r] = 0.9 * sum_e val[e] * x_t[col[e]] + 0.1 * x0[r]
__global__ __launch_bounds__(256) void k_prop(int it, float* __restrict__ dout) {
    const float* __restrict__ xin =
        (it == 0) ? g_x0 : ((it & 1) ? g_bufA : g_bufB);
    float* __restrict__ xout =
        (it == NUM_PROP - 1) ? dout : ((it & 1) ? g_bufB : g_bufA);

    int warp = (blockIdx.x * blockDim.x + threadIdx.x) >> 5;
    int lane = threadIdx.x & 31;
    if (warp >= N_NODES) return;

    int start = __ldg(&g_rowptr[warp]);
    int end   = __ldg(&g_rowptr[warp + 1]);

    float acc = 0.f;
    int e = start;
    for (; e + 1 < end; e += 2) {
        int2 c0 = __ldg(&g_edges[e]);
        int2 c1 = __ldg(&g_edges[e + 1]);
        float v0 = __ldg(&xin[(size_t)c0.x * D_OUT + lane]);
        float v1 = __ldg(&xin[(size_t)c1.x * D_OUT + lane]);
        acc += __int_as_float(c0.y) * v0;
        acc += __int_as_float(c1.y) * v1;
    }
    if (e < end) {
        int2 c0 = __ldg(&g_edges[e]);
        acc += __int_as_float(c0.y) * __ldg(&xin[(size_t)c0.x * D_OUT + lane]);
    }

    xout[(size_t)warp * D_OUT + lane] =
        (1.0f - ALPHA) * acc + ALPHA * __ldg(&g_x0[(size_t)warp * D_OUT + lane]);
}

// ---------------- launch ----------------
extern "C" void kernel_launch(void* const* d_in, const int* in_sizes, int n_in,
                              void* d_out, int out_size) {
    const float* F   = (const float*)d_in[0];
    const int*   row = (const int*)  d_in[1];
    const int*   col = (const int*)  d_in[2];
    const float* ev  = (const float*)d_in[3];
    const float* W1  = (const float*)d_in[4];
    const float* b1  = (const float*)d_in[5];
    const float* W2  = (const float*)d_in[6];
    const float* b2  = (const float*)d_in[7];
    float* out = (float*)d_out;

    // MLP head
    k_mlp1<<<(N_NODES + 127) / 128, 128>>>(F, W1, b1);
    k_mlp2<<<(N_NODES + 127) / 128, 128>>>(W2, b2);

    // CSR build (counting sort by row)
    k_zero_cnt<<<(N_NODES + 255) / 256, 256>>>();
    k_hist   <<<(N_EDGES + 255) / 256, 256>>>(row);
    k_scan   <<<1, 1024>>>();
    k_scatter<<<(N_EDGES + 255) / 256, 256>>>(row, col, ev);

    // 10 propagation rounds; last one writes d_out directly
    int warps_per_block = 256 / 32;
    int grid = (N_NODES + warps_per_block - 1) / warps_per_block;
    for (int it = 0; it < NUM_PROP; it++)
        k_prop<<<grid, 256>>>(it, out);
}

// round 2
// speedup vs baseline: 1.1495x; 1.1495x over previous
#include <cuda_runtime.h>

#define N_NODES 100000
#define N_EDGES 1600000
#define D_IN    256
#define D_HID   64
#define D_OUT   32
#define NUM_PROP 10
#define ALPHA   0.1f

#define SCAN_B   1024
#define NPART    ((N_NODES + SCAN_B - 1) / SCAN_B)   // 98

// ---------------- device scratch (no allocations allowed) ----------------
__device__ int   g_cnt[N_NODES];            // histogram, then scatter cursors
__device__ int   g_rowptr[N_NODES + 1];     // CSR row pointers
__device__ int   g_part[NPART];             // per-block sums
__device__ int   g_partpref[NPART];         // exclusive prefix of block sums
__device__ __align__(16) int2 g_edges[N_EDGES];   // (col, bits(val)), row-sorted
__device__ float g_H [(size_t)N_NODES * D_HID];
__device__ float g_x0[(size_t)N_NODES * D_OUT];
__device__ float g_bufA[(size_t)N_NODES * D_OUT];
__device__ float g_bufB[(size_t)N_NODES * D_OUT];

// ---------------- MLP stage 1: H = relu(F @ W1 + b1) ----------------
// 2 nodes per thread: W1 L1-resident loads amortized over 2 rows.
__global__ __launch_bounds__(128) void k_mlp1(const float* __restrict__ F,
                                              const float* __restrict__ W1,
                                              const float* __restrict__ b1) {
    int base  = blockIdx.x * 256;
    int node0 = base + threadIdx.x;
    int node1 = node0 + 128;
    bool has0 = node0 < N_NODES;
    bool has1 = node1 < N_NODES;
    if (!has0) return;

    float acc0[D_HID], acc1[D_HID];
#pragma unroll
    for (int h = 0; h < D_HID; h += 4) {
        float4 b = __ldg((const float4*)(b1 + h));
        acc0[h] = b.x; acc0[h+1] = b.y; acc0[h+2] = b.z; acc0[h+3] = b.w;
        acc1[h] = b.x; acc1[h+1] = b.y; acc1[h+2] = b.z; acc1[h+3] = b.w;
    }

    const float4* F0  = (const float4*)(F + (size_t)node0 * D_IN);
    const float4* F1  = (const float4*)(F + (size_t)(has1 ? node1 : node0) * D_IN);
    const float4* W14 = (const float4*)W1;

    for (int k4 = 0; k4 < D_IN / 4; k4++) {
        float4 f0 = __ldg(&F0[k4]);
        float4 f1 = __ldg(&F1[k4]);
        float f0v[4] = {f0.x, f0.y, f0.z, f0.w};
        float f1v[4] = {f1.x, f1.y, f1.z, f1.w};
#pragma unroll
        for (int s = 0; s < 4; s++) {
            int k = k4 * 4 + s;
            const float4* wrow = &W14[k * (D_HID / 4)];
#pragma unroll
            for (int j = 0; j < D_HID / 4; j++) {
                float4 w = __ldg(&wrow[j]);
                acc0[4*j]   += f0v[s] * w.x;
                acc0[4*j+1] += f0v[s] * w.y;
                acc0[4*j+2] += f0v[s] * w.z;
                acc0[4*j+3] += f0v[s] * w.w;
                acc1[4*j]   += f1v[s] * w.x;
                acc1[4*j+1] += f1v[s] * w.y;
                acc1[4*j+2] += f1v[s] * w.z;
                acc1[4*j+3] += f1v[s] * w.w;
            }
        }
    }

    float4* H0 = (float4*)(g_H + (size_t)node0 * D_HID);
#pragma unroll
    for (int j = 0; j < D_HID / 4; j++)
        H0[j] = make_float4(fmaxf(acc0[4*j],   0.f), fmaxf(acc0[4*j+1], 0.f),
                            fmaxf(acc0[4*j+2], 0.f), fmaxf(acc0[4*j+3], 0.f));
    if (has1) {
        float4* H1 = (float4*)(g_H + (size_t)node1 * D_HID);
#pragma unroll
        for (int j = 0; j < D_HID / 4; j++)
            H1[j] = make_float4(fmaxf(acc1[4*j],   0.f), fmaxf(acc1[4*j+1], 0.f),
                                fmaxf(acc1[4*j+2], 0.f), fmaxf(acc1[4*j+3], 0.f));
    }
}

// ---------------- MLP stage 2: x0 = H @ W2 + b2 ----------------
__global__ __launch_bounds__(128) void k_mlp2(const float* __restrict__ W2,
                                              const float* __restrict__ b2) {
    __shared__ float sW2[D_HID * D_OUT];
    for (int i = threadIdx.x; i < D_HID * D_OUT; i += 128) sW2[i] = W2[i];
    __syncthreads();

    int node = blockIdx.x * 128 + threadIdx.x;
    if (node >= N_NODES) return;

    float o[D_OUT];
#pragma unroll
    for (int c = 0; c < D_OUT; c++) o[c] = __ldg(&b2[c]);

    const float4* Hr = (const float4*)(g_H + (size_t)node * D_HID);
    for (int j = 0; j < D_HID / 4; j++) {
        float4 h4 = Hr[j];
        float hv[4] = {h4.x, h4.y, h4.z, h4.w};
#pragma unroll
        for (int s = 0; s < 4; s++) {
            const float* w = &sW2[(4*j + s) * D_OUT];
#pragma unroll
            for (int c = 0; c < D_OUT; c++) o[c] += hv[s] * w[c];
        }
    }

    float4* X = (float4*)(g_x0 + (size_t)node * D_OUT);
#pragma unroll
    for (int j = 0; j < D_OUT / 4; j++)
        X[j] = make_float4(o[4*j], o[4*j+1], o[4*j+2], o[4*j+3]);
}

// ---------------- CSR build ----------------
__global__ void k_zero_cnt() {
    int i = blockIdx.x * blockDim.x + threadIdx.x;
    if (i < N_NODES) g_cnt[i] = 0;
}

__global__ void k_hist(const int* __restrict__ row) {
    int e = blockIdx.x * blockDim.x + threadIdx.x;
    if (e < N_EDGES) atomicAdd(&g_cnt[row[e]], 1);
}

// --- parallel scan, 3 kernels ---
// 1) per-block sums
__global__ __launch_bounds__(SCAN_B) void k_blocksum() {
    int i = blockIdx.x * SCAN_B + threadIdx.x;
    int v = (i < N_NODES) ? g_cnt[i] : 0;
#pragma unroll
    for (int off = 16; off > 0; off >>= 1)
        v += __shfl_down_sync(0xffffffffu, v, off);
    __shared__ int ws[SCAN_B / 32];
    if ((threadIdx.x & 31) == 0) ws[threadIdx.x >> 5] = v;
    __syncthreads();
    if (threadIdx.x < SCAN_B / 32) {
        int w = ws[threadIdx.x];
#pragma unroll
        for (int off = 16; off > 0; off >>= 1)
            w += __shfl_down_sync(0xffffffffu, w, off);
        if (threadIdx.x == 0) g_part[blockIdx.x] = w;
    }
}

// 2) scan the NPART partials (one small block)
__global__ __launch_bounds__(128) void k_scanpart() {
    __shared__ int s[NPART];
    int tid = threadIdx.x;
    if (tid < NPART) s[tid] = g_part[tid];
    __syncthreads();
    if (tid == 0) {
        int run = 0;
        for (int b = 0; b < NPART; b++) { int v = s[b]; s[b] = run; run += v; }
        g_rowptr[N_NODES] = run;   // == N_EDGES
    }
    __syncthreads();
    if (tid < NPART) g_partpref[tid] = s[tid];
}

// 3) block-local exclusive scan + global offset -> rowptr + cursors
__global__ __launch_bounds__(SCAN_B) void k_scanfinal() {
    int i   = blockIdx.x * SCAN_B + threadIdx.x;
    int val = (i < N_NODES) ? g_cnt[i] : 0;
    int lane = threadIdx.x & 31, wid = threadIdx.x >> 5;

    int v = val;
#pragma unroll
    for (int off = 1; off < 32; off <<= 1) {
        int t = __shfl_up_sync(0xffffffffu, v, off);
        if (lane >= off) v += t;
    }
    __shared__ int ws[SCAN_B / 32];
    if (lane == 31) ws[wid] = v;
    __syncthreads();
    if (wid == 0) {
        int w = (lane < SCAN_B / 32) ? ws[lane] : 0;
#pragma unroll
        for (int off = 1; off < 32; off <<= 1) {
            int t = __shfl_up_sync(0xffffffffu, w, off);
            if (lane >= off) w += t;
        }
        if (lane < SCAN_B / 32) ws[lane] = w;
    }
    __syncthreads();

    int excl = v - val + (wid ? ws[wid - 1] : 0) + g_partpref[blockIdx.x];
    if (i < N_NODES) {
        g_rowptr[i] = excl;
        g_cnt[i]    = excl;   // scatter cursor
    }
}

__global__ void k_scatter(const int* __restrict__ row,
                          const int* __restrict__ col,
                          const float* __restrict__ val) {
    int e = blockIdx.x * blockDim.x + threadIdx.x;
    if (e < N_EDGES) {
        int r = row[e];
        int p = atomicAdd(&g_cnt[r], 1);
        g_edges[p] = make_int2(col[e], __float_as_int(val[e]));
    }
}

// ---------------- propagation: warp-per-row, lane = output dim ----------------
__global__ __launch_bounds__(256) void k_prop(int it, float* __restrict__ dout) {
    const float* __restrict__ xin =
        (it == 0) ? g_x0 : ((it & 1) ? g_bufA : g_bufB);
    float* __restrict__ xout =
        (it == NUM_PROP - 1) ? dout : ((it & 1) ? g_bufB : g_bufA);

    int warp = (blockIdx.x * blockDim.x + threadIdx.x) >> 5;
    int lane = threadIdx.x & 31;
    if (warp >= N_NODES) return;

    int start = __ldg(&g_rowptr[warp]);
    int end   = __ldg(&g_rowptr[warp + 1]);

    float acc = 0.f;
    int e = start;

    // align to even edge index for int4 (2-edge) loads
    if ((e & 1) && e < end) {
        int2 c = __ldg(&g_edges[e]);
        acc += __int_as_float(c.y) * __ldg(&xin[(size_t)c.x * D_OUT + lane]);
        e++;
    }
    // 4 edges (2× LDG.128) per iteration -> 4 independent 128B gathers in flight
    for (; e + 3 < end; e += 4) {
        int4 p0 = __ldg((const int4*)&g_edges[e]);
        int4 p1 = __ldg((const int4*)&g_edges[e + 2]);
        float v0 = __ldg(&xin[(size_t)p0.x * D_OUT + lane]);
        float v1 = __ldg(&xin[(size_t)p0.z * D_OUT + lane]);
        float v2 = __ldg(&xin[(size_t)p1.x * D_OUT + lane]);
        float v3 = __ldg(&xin[(size_t)p1.z * D_OUT + lane]);
        acc += __int_as_float(p0.y) * v0;
        acc += __int_as_float(p0.w) * v1;
        acc += __int_as_float(p1.y) * v2;
        acc += __int_as_float(p1.w) * v3;
    }
    if (e + 1 < end) {
        int4 p0 = __ldg((const int4*)&g_edges[e]);
        acc += __int_as_float(p0.y) * __ldg(&xin[(size_t)p0.x * D_OUT + lane]);
        acc += __int_as_float(p0.w) * __ldg(&xin[(size_t)p0.z * D_OUT + lane]);
        e += 2;
    }
    if (e < end) {
        int2 c = __ldg(&g_edges[e]);
        acc += __int_as_float(c.y) * __ldg(&xin[(size_t)c.x * D_OUT + lane]);
    }

    xout[(size_t)warp * D_OUT + lane] =
        (1.0f - ALPHA) * acc + ALPHA * __ldg(&g_x0[(size_t)warp * D_OUT + lane]);
}

// ---------------- launch ----------------
extern "C" void kernel_launch(void* const* d_in, const int* in_sizes, int n_in,
                              void* d_out, int out_size) {
    const float* F   = (const float*)d_in[0];
    const int*   row = (const int*)  d_in[1];
    const int*   col = (const int*)  d_in[2];
    const float* ev  = (const float*)d_in[3];
    const float* W1  = (const float*)d_in[4];
    const float* b1  = (const float*)d_in[5];
    const float* W2  = (const float*)d_in[6];
    const float* b2  = (const float*)d_in[7];
    float* out = (float*)d_out;

    // MLP head
    k_mlp1<<<(N_NODES + 255) / 256, 128>>>(F, W1, b1);
    k_mlp2<<<(N_NODES + 127) / 128, 128>>>(W2, b2);

    // CSR build (counting sort by row) with parallel 3-phase scan
    k_zero_cnt <<<(N_NODES + 255) / 256, 256>>>();
    k_hist     <<<(N_EDGES + 255) / 256, 256>>>(row);
    k_blocksum <<<NPART, SCAN_B>>>();
    k_scanpart <<<1, 128>>>();
    k_scanfinal<<<NPART, SCAN_B>>>();
    k_scatter  <<<(N_EDGES + 255) / 256, 256>>>(row, col, ev);

    // 10 propagation rounds; last writes d_out directly
    int warps_per_block = 256 / 32;
    int grid = (N_NODES + warps_per_block - 1) / warps_per_block;
    for (int it = 0; it < NUM_PROP; it++)
        k_prop<<<grid, 256>>>(it, out);
}

// round 4
// speedup vs baseline: 1.7162x; 1.4930x over previous
#include <cuda_runtime.h>

#define N_NODES 100000
#define N_EDGES 1600000
#define D_IN    256
#define D_HID   64
#define D_OUT   32
#define NUM_PROP 10
#define ALPHA   0.1f

#define SCAN_B   1024
#define NPART    ((N_NODES + SCAN_B - 1) / SCAN_B)   // 98

typedef unsigned long long u64;

// ---------------- device scratch (no allocations allowed) ----------------
__device__ int   g_cnt[N_NODES];
__device__ int   g_rowptr[N_NODES + 1];
__device__ int   g_part[NPART];
__device__ int   g_partpref[NPART];
__device__ __align__(16) int2 g_edges[N_EDGES];
__device__ __align__(16) float g_x0[(size_t)N_NODES * D_OUT];
__device__ __align__(16) float g_bufA[(size_t)N_NODES * D_OUT];
__device__ __align__(16) float g_bufB[(size_t)N_NODES * D_OUT];

// ---------------- packed fp32x2 helpers (sm_103a) ----------------
__device__ __forceinline__ u64 fma2(u64 a, u64 b, u64 c) {
    u64 d;
    asm("fma.rn.f32x2 %0, %1, %2, %3;" : "=l"(d) : "l"(a), "l"(b), "l"(c));
    return d;
}
__device__ __forceinline__ u64 pack2(float x) {
    u64 d;
    asm("mov.b64 %0, {%1, %1};" : "=l"(d) : "f"(x));
    return d;
}
__device__ __forceinline__ float2 unpack2(u64 p) {
    float2 r;
    asm("mov.b64 {%0, %1}, %2;" : "=f"(r.x), "=f"(r.y) : "l"(p));
    return r;
}

// ---------------- fused MLP: x0 = relu(F @ W1 + b1) @ W2 + b2 ----------------
// One node per thread. W1 (64KB) + W2 (8KB) staged in dynamic shared memory;
// all FMAs are packed f32x2 (2 MACs/slot).
__global__ __launch_bounds__(128) void k_mlp(const float* __restrict__ F,
                                             const float* __restrict__ W1,
                                             const float* __restrict__ b1,
                                             const float* __restrict__ W2,
                                             const float* __restrict__ b2) {
    extern __shared__ float smem[];
    float* sW1 = smem;                 // [256][64]
    float* sW2 = smem + D_IN * D_HID;  // [64][32]

    {
        const float4* src1 = (const float4*)W1;
        float4* dst1 = (float4*)sW1;
        for (int i = threadIdx.x; i < D_IN * D_HID / 4; i += 128) dst1[i] = src1[i];
        const float4* src2 = (const float4*)W2;
        float4* dst2 = (float4*)sW2;
        for (int i = threadIdx.x; i < D_HID * D_OUT / 4; i += 128) dst2[i] = src2[i];
    }
    __syncthreads();

    int node = blockIdx.x * 128 + threadIdx.x;
    if (node >= N_NODES) return;

    // ---- stage 1: acc[p] = packed pair (2p, 2p+1) of hidden pre-activation
    u64 acc[D_HID / 2];
    {
        const u64* b1p = (const u64*)b1;
#pragma unroll
        for (int p = 0; p < D_HID / 2; p++) acc[p] = __ldg(&b1p[p]);
    }

    const float4* Fr = (const float4*)(F + (size_t)node * D_IN);
    for (int k4 = 0; k4 < D_IN / 4; k4++) {
        float4 f = __ldg(&Fr[k4]);
        float fv[4] = {f.x, f.y, f.z, f.w};
#pragma unroll
        for (int s = 0; s < 4; s++) {
            int k = k4 * 4 + s;
            u64 fp = pack2(fv[s]);
            const u64* wrow = (const u64*)(sW1 + k * D_HID);
#pragma unroll
            for (int p = 0; p < D_HID / 2; p++)
                acc[p] = fma2(fp, wrow[p], acc[p]);
        }
    }

    // ---- stage 2: o[q] = packed pair (2q, 2q+1) of output
    u64 o[D_OUT / 2];
    {
        const u64* b2p = (const u64*)b2;
#pragma unroll
        for (int q = 0; q < D_OUT / 2; q++) o[q] = __ldg(&b2p[q]);
    }

#pragma unroll
    for (int p = 0; p < D_HID / 2; p++) {
        float2 h = unpack2(acc[p]);
        float ha = fmaxf(h.x, 0.f);
        float hb = fmaxf(h.y, 0.f);
        u64 hap = pack2(ha);
        u64 hbp = pack2(hb);
        const u64* w2a = (const u64*)(sW2 + (2 * p)     * D_OUT);
        const u64* w2b = (const u64*)(sW2 + (2 * p + 1) * D_OUT);
#pragma unroll
        for (int q = 0; q < D_OUT / 2; q++) {
            o[q] = fma2(hap, w2a[q], o[q]);
            o[q] = fma2(hbp, w2b[q], o[q]);
        }
    }

    ulonglong2* X = (ulonglong2*)(g_x0 + (size_t)node * D_OUT);
#pragma unroll
    for (int q2 = 0; q2 < D_OUT / 4; q2++)
        X[q2] = make_ulonglong2(o[2 * q2], o[2 * q2 + 1]);
}

// ---------------- CSR build ----------------
__global__ void k_zero_cnt() {
    int i = blockIdx.x * blockDim.x + threadIdx.x;
    if (i < N_NODES) g_cnt[i] = 0;
}

__global__ void k_hist(const int* __restrict__ row) {
    int e = blockIdx.x * blockDim.x + threadIdx.x;
    if (e < N_EDGES) atomicAdd(&g_cnt[row[e]], 1);
}

__global__ __launch_bounds__(SCAN_B) void k_blocksum() {
    int i = blockIdx.x * SCAN_B + threadIdx.x;
    int v = (i < N_NODES) ? g_cnt[i] : 0;
#pragma unroll
    for (int off = 16; off > 0; off >>= 1)
        v += __shfl_down_sync(0xffffffffu, v, off);
    __shared__ int ws[SCAN_B / 32];
    if ((threadIdx.x & 31) == 0) ws[threadIdx.x >> 5] = v;
    __syncthreads();
    if (threadIdx.x < SCAN_B / 32) {
        int w = ws[threadIdx.x];
#pragma unroll
        for (int off = 16; off > 0; off >>= 1)
            w += __shfl_down_sync(0xffffffffu, w, off);
        if (threadIdx.x == 0) g_part[blockIdx.x] = w;
    }
}

__global__ __launch_bounds__(128) void k_scanpart() {
    __shared__ int s[NPART];
    int tid = threadIdx.x;
    if (tid < NPART) s[tid] = g_part[tid];
    __syncthreads();
    if (tid == 0) {
        int run = 0;
        for (int b = 0; b < NPART; b++) { int v = s[b]; s[b] = run; run += v; }
        g_rowptr[N_NODES] = run;
    }
    __syncthreads();
    if (tid < NPART) g_partpref[tid] = s[tid];
}

__global__ __launch_bounds__(SCAN_B) void k_scanfinal() {
    int i    = blockIdx.x * SCAN_B + threadIdx.x;
    int val  = (i < N_NODES) ? g_cnt[i] : 0;
    int lane = threadIdx.x & 31, wid = threadIdx.x >> 5;

    int v = val;
#pragma unroll
    for (int off = 1; off < 32; off <<= 1) {
        int t = __shfl_up_sync(0xffffffffu, v, off);
        if (lane >= off) v += t;
    }
    __shared__ int ws[SCAN_B / 32];
    if (lane == 31) ws[wid] = v;
    __syncthreads();
    if (wid == 0) {
        int w = (lane < SCAN_B / 32) ? ws[lane] : 0;
#pragma unroll
        for (int off = 1; off < 32; off <<= 1) {
            int t = __shfl_up_sync(0xffffffffu, w, off);
            if (lane >= off) w += t;
        }
        if (lane < SCAN_B / 32) ws[lane] = w;
    }
    __syncthreads();

    int excl = v - val + (wid ? ws[wid - 1] : 0) + g_partpref[blockIdx.x];
    if (i < N_NODES) {
        g_rowptr[i] = excl;
        g_cnt[i]    = excl;
    }
}

__global__ void k_scatter(const int* __restrict__ row,
                          const int* __restrict__ col,
                          const float* __restrict__ val) {
    int e = blockIdx.x * blockDim.x + threadIdx.x;
    if (e < N_EDGES) {
        int r = row[e];
        int p = atomicAdd(&g_cnt[r], 1);
        g_edges[p] = make_int2(col[e], __float_as_int(val[e]));
    }
}

// ---------------- propagation: warp-per-row, lane = dim, 8 gathers in flight ----------------
__global__ __launch_bounds__(256) void k_prop(int it, float* __restrict__ dout) {
    const float* __restrict__ xin =
        (it == 0) ? g_x0 : ((it & 1) ? g_bufA : g_bufB);
    float* __restrict__ xout =
        (it == NUM_PROP - 1) ? dout : ((it & 1) ? g_bufB : g_bufA);

    int warp = (blockIdx.x * blockDim.x + threadIdx.x) >> 5;
    int lane = threadIdx.x & 31;
    if (warp >= N_NODES) return;

    int start = __ldg(&g_rowptr[warp]);
    int end   = __ldg(&g_rowptr[warp + 1]);

    float acc = 0.f;
    int e = start;

    // align to even index for 2-edge LDG.128
    if ((e & 1) && e < end) {
        int2 c = __ldg(&g_edges[e]);
        acc += __int_as_float(c.y) * __ldg(&xin[(size_t)c.x * D_OUT + lane]);
        e++;
    }
    // 8 edges (4x LDG.128) per iteration: 8 independent 128B gathers in flight
    for (; e + 7 < end; e += 8) {
        int4 p0 = __ldg((const int4*)&g_edges[e]);
        int4 p1 = __ldg((const int4*)&g_edges[e + 2]);
        int4 p2 = __ldg((const int4*)&g_edges[e + 4]);
        int4 p3 = __ldg((const int4*)&g_edges[e + 6]);
        float v0 = __ldg(&xin[(size_t)p0.x * D_OUT + lane]);
        float v1 = __ldg(&xin[(size_t)p0.z * D_OUT + lane]);
        float v2 = __ldg(&xin[(size_t)p1.x * D_OUT + lane]);
        float v3 = __ldg(&xin[(size_t)p1.z * D_OUT + lane]);
        float v4 = __ldg(&xin[(size_t)p2.x * D_OUT + lane]);
        float v5 = __ldg(&xin[(size_t)p2.z * D_OUT + lane]);
        float v6 = __ldg(&xin[(size_t)p3.x * D_OUT + lane]);
        float v7 = __ldg(&xin[(size_t)p3.z * D_OUT + lane]);
        acc += __int_as_float(p0.y) * v0;
        acc += __int_as_float(p0.w) * v1;
        acc += __int_as_float(p1.y) * v2;
        acc += __int_as_float(p1.w) * v3;
        acc += __int_as_float(p2.y) * v4;
        acc += __int_as_float(p2.w) * v5;
        acc += __int_as_float(p3.y) * v6;
        acc += __int_as_float(p3.w) * v7;
    }
    for (; e + 1 < end; e += 2) {
        int4 p0 = __ldg((const int4*)&g_edges[e]);
        float v0 = __ldg(&xin[(size_t)p0.x * D_OUT + lane]);
        float v1 = __ldg(&xin[(size_t)p0.z * D_OUT + lane]);
        acc += __int_as_float(p0.y) * v0;
        acc += __int_as_float(p0.w) * v1;
    }
    if (e < end) {
        int2 c = __ldg(&g_edges[e]);
        acc += __int_as_float(c.y) * __ldg(&xin[(size_t)c.x * D_OUT + lane]);
    }

    xout[(size_t)warp * D_OUT + lane] =
        (1.0f - ALPHA) * acc + ALPHA * __ldg(&g_x0[(size_t)warp * D_OUT + lane]);
}

// ---------------- launch ----------------
extern "C" void kernel_launch(void* const* d_in, const int* in_sizes, int n_in,
                              void* d_out, int out_size) {
    const float* F   = (const float*)d_in[0];
    const int*   row = (const int*)  d_in[1];
    const int*   col = (const int*)  d_in[2];
    const float* ev  = (const float*)d_in[3];
    const float* W1  = (const float*)d_in[4];
    const float* b1  = (const float*)d_in[5];
    const float* W2  = (const float*)d_in[6];
    const float* b2  = (const float*)d_in[7];
    float* out = (float*)d_out;

    const int MLP_SMEM = (D_IN * D_HID + D_HID * D_OUT) * sizeof(float);  // 72 KB
    static bool attr_set = false;
    if (!attr_set) {
        cudaFuncSetAttribute(k_mlp, cudaFuncAttributeMaxDynamicSharedMemorySize, MLP_SMEM);
        attr_set = true;
    }

    // fused MLP head
    k_mlp<<<(N_NODES + 127) / 128, 128, MLP_SMEM>>>(F, W1, b1, W2, b2);

    // CSR build (counting sort by row)
    k_zero_cnt <<<(N_NODES + 255) / 256, 256>>>();
    k_hist     <<<(N_EDGES + 255) / 256, 256>>>(row);
    k_blocksum <<<NPART, SCAN_B>>>();
    k_scanpart <<<1, 128>>>();
    k_scanfinal<<<NPART, SCAN_B>>>();
    k_scatter  <<<(N_EDGES + 255) / 256, 256>>>(row, col, ev);

    // 10 propagation rounds; last writes d_out directly
    int warps_per_block = 256 / 32;
    int grid = (N_NODES + warps_per_block - 1) / warps_per_block;
    for (int it = 0; it < NUM_PROP; it++)
        k_prop<<<grid, 256>>>(it, out);
}

// round 5
// speedup vs baseline: 1.8926x; 1.1028x over previous
#include <cuda_runtime.h>

#define N_NODES 100000
#define N_EDGES 1600000
#define D_IN    256
#define D_HID   64
#define D_OUT   32
#define NUM_PROP 10
#define ALPHA   0.1f

#define SCAN_B   1024
#define NPART    ((N_NODES + SCAN_B - 1) / SCAN_B)   // 98

typedef unsigned long long u64;

// ---------------- device scratch (no allocations allowed) ----------------
__device__ int   g_cnt[N_NODES];
__device__ int   g_rowptr[N_NODES + 1];
__device__ int   g_part[NPART];
__device__ int   g_partpref[NPART];
__device__ __align__(16) int2 g_edges[N_EDGES];
__device__ __align__(16) float g_x0[(size_t)N_NODES * D_OUT];
__device__ __align__(16) float g_bufA[(size_t)N_NODES * D_OUT];
__device__ __align__(16) float g_bufB[(size_t)N_NODES * D_OUT];

// ---------------- packed fp32x2 helpers (sm_103a) ----------------
__device__ __forceinline__ u64 fma2(u64 a, u64 b, u64 c) {
    u64 d;
    asm("fma.rn.f32x2 %0, %1, %2, %3;" : "=l"(d) : "l"(a), "l"(b), "l"(c));
    return d;
}
__device__ __forceinline__ u64 pack2(float x) {
    u64 d;
    asm("mov.b64 %0, {%1, %1};" : "=l"(d) : "f"(x));
    return d;
}
__device__ __forceinline__ float2 unpack2(u64 p) {
    float2 r;
    asm("mov.b64 {%0, %1}, %2;" : "=f"(r.x), "=f"(r.y) : "l"(p));
    return r;
}

// ---------------- fused MLP: x0 = relu(F @ W1 + b1) @ W2 + b2 ----------------
__global__ __launch_bounds__(128) void k_mlp(const float* __restrict__ F,
                                             const float* __restrict__ W1,
                                             const float* __restrict__ b1,
                                             const float* __restrict__ W2,
                                             const float* __restrict__ b2) {
    extern __shared__ float smem[];
    float* sW1 = smem;                 // [256][64]
    float* sW2 = smem + D_IN * D_HID;  // [64][32]

    {
        const float4* src1 = (const float4*)W1;
        float4* dst1 = (float4*)sW1;
        for (int i = threadIdx.x; i < D_IN * D_HID / 4; i += 128) dst1[i] = src1[i];
        const float4* src2 = (const float4*)W2;
        float4* dst2 = (float4*)sW2;
        for (int i = threadIdx.x; i < D_HID * D_OUT / 4; i += 128) dst2[i] = src2[i];
    }
    __syncthreads();

    int node = blockIdx.x * 128 + threadIdx.x;
    if (node >= N_NODES) return;

    u64 acc[D_HID / 2];
    {
        const u64* b1p = (const u64*)b1;
#pragma unroll
        for (int p = 0; p < D_HID / 2; p++) acc[p] = __ldg(&b1p[p]);
    }

    const float4* Fr = (const float4*)(F + (size_t)node * D_IN);
    for (int k4 = 0; k4 < D_IN / 4; k4++) {
        float4 f = __ldg(&Fr[k4]);
        float fv[4] = {f.x, f.y, f.z, f.w};
#pragma unroll
        for (int s = 0; s < 4; s++) {
            int k = k4 * 4 + s;
            u64 fp = pack2(fv[s]);
            const u64* wrow = (const u64*)(sW1 + k * D_HID);
#pragma unroll
            for (int p = 0; p < D_HID / 2; p++)
                acc[p] = fma2(fp, wrow[p], acc[p]);
        }
    }

    u64 o[D_OUT / 2];
    {
        const u64* b2p = (const u64*)b2;
#pragma unroll
        for (int q = 0; q < D_OUT / 2; q++) o[q] = __ldg(&b2p[q]);
    }

#pragma unroll
    for (int p = 0; p < D_HID / 2; p++) {
        float2 h = unpack2(acc[p]);
        u64 hap = pack2(fmaxf(h.x, 0.f));
        u64 hbp = pack2(fmaxf(h.y, 0.f));
        const u64* w2a = (const u64*)(sW2 + (2 * p)     * D_OUT);
        const u64* w2b = (const u64*)(sW2 + (2 * p + 1) * D_OUT);
#pragma unroll
        for (int q = 0; q < D_OUT / 2; q++) {
            o[q] = fma2(hap, w2a[q], o[q]);
            o[q] = fma2(hbp, w2b[q], o[q]);
        }
    }

    ulonglong2* X = (ulonglong2*)(g_x0 + (size_t)node * D_OUT);
#pragma unroll
    for (int q2 = 0; q2 < D_OUT / 4; q2++)
        X[q2] = make_ulonglong2(o[2 * q2], o[2 * q2 + 1]);
}

// ---------------- CSR build ----------------
__global__ void k_zero_cnt() {
    int i = blockIdx.x * blockDim.x + threadIdx.x;
    if (i < N_NODES) g_cnt[i] = 0;
}

__global__ void k_hist(const int* __restrict__ row) {
    int e = blockIdx.x * blockDim.x + threadIdx.x;
    if (e < N_EDGES) atomicAdd(&g_cnt[row[e]], 1);
}

__global__ __launch_bounds__(SCAN_B) void k_blocksum() {
    int i = blockIdx.x * SCAN_B + threadIdx.x;
    int v = (i < N_NODES) ? g_cnt[i] : 0;
#pragma unroll
    for (int off = 16; off > 0; off >>= 1)
        v += __shfl_down_sync(0xffffffffu, v, off);
    __shared__ int ws[SCAN_B / 32];
    if ((threadIdx.x & 31) == 0) ws[threadIdx.x >> 5] = v;
    __syncthreads();
    if (threadIdx.x < SCAN_B / 32) {
        int w = ws[threadIdx.x];
#pragma unroll
        for (int off = 16; off > 0; off >>= 1)
            w += __shfl_down_sync(0xffffffffu, w, off);
        if (threadIdx.x == 0) g_part[blockIdx.x] = w;
    }
}

__global__ __launch_bounds__(128) void k_scanpart() {
    __shared__ int s[NPART];
    int tid = threadIdx.x;
    if (tid < NPART) s[tid] = g_part[tid];
    __syncthreads();
    if (tid == 0) {
        int run = 0;
        for (int b = 0; b < NPART; b++) { int v = s[b]; s[b] = run; run += v; }
        g_rowptr[N_NODES] = run;
    }
    __syncthreads();
    if (tid < NPART) g_partpref[tid] = s[tid];
}

__global__ __launch_bounds__(SCAN_B) void k_scanfinal() {
    int i    = blockIdx.x * SCAN_B + threadIdx.x;
    int val  = (i < N_NODES) ? g_cnt[i] : 0;
    int lane = threadIdx.x & 31, wid = threadIdx.x >> 5;

    int v = val;
#pragma unroll
    for (int off = 1; off < 32; off <<= 1) {
        int t = __shfl_up_sync(0xffffffffu, v, off);
        if (lane >= off) v += t;
    }
    __shared__ int ws[SCAN_B / 32];
    if (lane == 31) ws[wid] = v;
    __syncthreads();
    if (wid == 0) {
        int w = (lane < SCAN_B / 32) ? ws[lane] : 0;
#pragma unroll
        for (int off = 1; off < 32; off <<= 1) {
            int t = __shfl_up_sync(0xffffffffu, w, off);
            if (lane >= off) w += t;
        }
        if (lane < SCAN_B / 32) ws[lane] = w;
    }
    __syncthreads();

    int excl = v - val + (wid ? ws[wid - 1] : 0) + g_partpref[blockIdx.x];
    if (i < N_NODES) {
        g_rowptr[i] = excl;
        g_cnt[i]    = excl;
    }
}

__global__ void k_scatter(const int* __restrict__ row,
                          const int* __restrict__ col,
                          const float* __restrict__ val) {
    int e = blockIdx.x * blockDim.x + threadIdx.x;
    if (e < N_EDGES) {
        int r = row[e];
        int p = atomicAdd(&g_cnt[r], 1);
        g_edges[p] = make_int2(col[e], __float_as_int(val[e]));
    }
}

// ---------------- propagation: warp-per-row, lane = dim, 16 gathers in flight ----------------
__global__ __launch_bounds__(256) void k_prop(int it, float* __restrict__ dout) {
    const float* __restrict__ xin =
        (it == 0) ? g_x0 : ((it & 1) ? g_bufA : g_bufB);
    float* __restrict__ xout =
        (it == NUM_PROP - 1) ? dout : ((it & 1) ? g_bufB : g_bufA);

    int warp = (blockIdx.x * blockDim.x + threadIdx.x) >> 5;
    int lane = threadIdx.x & 31;
    if (warp >= N_NODES) return;

    int start = __ldg(&g_rowptr[warp]);
    int end   = __ldg(&g_rowptr[warp + 1]);

    const float* __restrict__ xl = xin + lane;   // lane-adjusted base

    float acc = 0.f;
    int e = start;

    if ((e & 1) && e < end) {
        int2 c = __ldg(&g_edges[e]);
        acc += __int_as_float(c.y) * __ldg(&xl[(size_t)c.x * D_OUT]);
        e++;
    }
    // 16 edges (8x LDG.128 edge loads) per iter: 16 independent 128B gathers in flight
    for (; e + 15 < end; e += 16) {
        int4 p[8];
#pragma unroll
        for (int j = 0; j < 8; j++) p[j] = __ldg((const int4*)&g_edges[e + 2 * j]);
        float v[16];
#pragma unroll
        for (int j = 0; j < 8; j++) {
            v[2*j]   = __ldg(&xl[(size_t)p[j].x * D_OUT]);
            v[2*j+1] = __ldg(&xl[(size_t)p[j].z * D_OUT]);
        }
#pragma unroll
        for (int j = 0; j < 8; j++) {
            acc += __int_as_float(p[j].y) * v[2*j];
            acc += __int_as_float(p[j].w) * v[2*j+1];
        }
    }
    for (; e + 3 < end; e += 4) {
        int4 p0 = __ldg((const int4*)&g_edges[e]);
        int4 p1 = __ldg((const int4*)&g_edges[e + 2]);
        float v0 = __ldg(&xl[(size_t)p0.x * D_OUT]);
        float v1 = __ldg(&xl[(size_t)p0.z * D_OUT]);
        float v2 = __ldg(&xl[(size_t)p1.x * D_OUT]);
        float v3 = __ldg(&xl[(size_t)p1.z * D_OUT]);
        acc += __int_as_float(p0.y) * v0;
        acc += __int_as_float(p0.w) * v1;
        acc += __int_as_float(p1.y) * v2;
        acc += __int_as_float(p1.w) * v3;
    }
    if (e + 1 < end) {
        int4 p0 = __ldg((const int4*)&g_edges[e]);
        acc += __int_as_float(p0.y) * __ldg(&xl[(size_t)p0.x * D_OUT]);
        acc += __int_as_float(p0.w) * __ldg(&xl[(size_t)p0.z * D_OUT]);
        e += 2;
    }
    if (e < end) {
        int2 c = __ldg(&g_edges[e]);
        acc += __int_as_float(c.y) * __ldg(&xl[(size_t)c.x * D_OUT]);
    }

    xout[(size_t)warp * D_OUT + lane] =
        (1.0f - ALPHA) * acc + ALPHA * __ldg(&g_x0[(size_t)warp * D_OUT + lane]);
}

// ---------------- launch ----------------
extern "C" void kernel_launch(void* const* d_in, const int* in_sizes, int n_in,
                              void* d_out, int out_size) {
    const float* F   = (const float*)d_in[0];
    const int*   row = (const int*)  d_in[1];
    const int*   col = (const int*)  d_in[2];
    const float* ev  = (const float*)d_in[3];
    const float* W1  = (const float*)d_in[4];
    const float* b1  = (const float*)d_in[5];
    const float* W2  = (const float*)d_in[6];
    const float* b2  = (const float*)d_in[7];
    float* out = (float*)d_out;

    const int MLP_SMEM = (D_IN * D_HID + D_HID * D_OUT) * sizeof(float);  // 72 KB
    cudaFuncSetAttribute(k_mlp, cudaFuncAttributeMaxDynamicSharedMemorySize, MLP_SMEM);

    // Fork: CSR build on a side stream, MLP on the main (capture) stream.
    // Stream/event setup happens only at capture time — the replayed graph
    // contains just the kernel nodes with the fork/join dependencies.
    cudaStream_t side;
    cudaEvent_t evFork, evJoin;
    cudaStreamCreateWithFlags(&side, cudaStreamNonBlocking);
    cudaEventCreateWithFlags(&evFork, cudaEventDisableTiming);
    cudaEventCreateWithFlags(&evJoin, cudaEventDisableTiming);

    cudaEventRecord(evFork, 0);              // fork point on capture stream
    cudaStreamWaitEvent(side, evFork, 0);

    // main stream: fused MLP head (FMA-bound)
    k_mlp<<<(N_NODES + 127) / 128, 128, MLP_SMEM>>>(F, W1, b1, W2, b2);

    // side stream: CSR build (memory/atomic-bound)
    k_zero_cnt <<<(N_NODES + 255) / 256, 256, 0, side>>>();
    k_hist     <<<(N_EDGES + 255) / 256, 256, 0, side>>>(row);
    k_blocksum <<<NPART, SCAN_B, 0, side>>>();
    k_scanpart <<<1, 128, 0, side>>>();
    k_scanfinal<<<NPART, SCAN_B, 0, side>>>();
    k_scatter  <<<(N_EDGES + 255) / 256, 256, 0, side>>>(row, col, ev);

    cudaEventRecord(evJoin, side);           // join back into capture stream
    cudaStreamWaitEvent(0, evJoin, 0);

    cudaEventDestroy(evFork);
    cudaEventDestroy(evJoin);
    cudaStreamDestroy(side);

    // 10 propagation rounds; last writes d_out directly
    int warps_per_block = 256 / 32;
    int grid = (N_NODES + warps_per_block - 1) / warps_per_block;
    for (int it = 0; it < NUM_PROP; it++)
        k_prop<<<grid, 256>>>(it, out);
}